// round 10
// baseline (speedup 1.0000x reference)
#include <cuda_runtime.h>

// Inputs (metadata order):
//  0: link_pos_seq   [1024,32,8,3]    f32
//  1: link_rot_seq   [1024,32,8,3,3]  f32
//  2: sphere_centers [8,8,3]          f32
//  3: sphere_radii   [8,8]            f32
//  4: sdf_grid       [256,256,256]    f32
//  5: weight         scalar           f32
// Output: [1024,32] f32

#define GRID_N 256
#define N_LINKS 8
#define N_SPH 8
#define TB 256

// Faithfully-rounded t/0.01 (mul + 2 fma Newton correction).
__device__ __forceinline__ float div001(float t) {
    const float q0 = t * 100.0f;
    return fmaf(fmaf(-0.01f, q0, t), 100.0f, q0);
}

__device__ __forceinline__ int vox(float t) {
    int i = (int)floorf(div001(t + 1.28f));
    return min(max(i, 0), GRID_N - 1);
}

// Split-warp gather: two complementary half-warp-predicated LDGs so each SASS
// LDG touches ~16 divergent lines instead of ~32 (within-LDG replays at
// 2.07 cyc/wf -> cross-LDG streaming at ~1.0 cyc/wf).
__device__ __forceinline__ float gather_split(const float* addr, int lane) {
    float v;
    asm volatile(
        "{\n\t"
        ".reg .pred p;\n\t"
        "setp.lt.s32 p, %1, 16;\n\t"
        "@p  ld.global.nc.f32 %0, [%2];\n\t"
        "@!p ld.global.nc.f32 %0, [%2];\n\t"
        "}"
        : "=f"(v) : "r"(lane), "l"(addr));
    return v;
}

__global__ __launch_bounds__(TB, 8)
void voxel_collision_kernel(const float* __restrict__ pos,
                            const float* __restrict__ rot,
                            const float* __restrict__ cen,
                            const float* __restrict__ rad,
                            const float* __restrict__ sdf,
                            const float* __restrict__ wptr,
                            float* __restrict__ out) {
    __shared__ float s_cen[N_LINKS * N_SPH * 3];   // 768 B
    __shared__ float s_rad[N_LINKS * N_SPH];       // 256 B

    const int tid = threadIdx.x;
    if (tid < N_LINKS * N_SPH * 3) s_cen[tid] = cen[tid];
    if (tid < N_LINKS * N_SPH)     s_rad[tid] = rad[tid];
    __syncthreads();

    const int g = blockIdx.x * TB + tid;           // bh*8 + l
    const int l = g & 7;
    const int lane = tid & 31;

    const float* R = rot + (size_t)g * 9;
    const float r00 = __ldg(R + 0), r01 = __ldg(R + 1), r02 = __ldg(R + 2);
    const float r10 = __ldg(R + 3), r11 = __ldg(R + 4), r12 = __ldg(R + 5);
    const float r20 = __ldg(R + 6), r21 = __ldg(R + 7), r22 = __ldg(R + 8);
    const float* P = pos + (size_t)g * 3;
    const float px = __ldg(P + 0), py = __ldg(P + 1), pz = __ldg(P + 2);

    const float* lc = s_cen + l * (N_SPH * 3);
    const float* lr = s_rad + l * N_SPH;

    // 8 mutually independent gathers; each issued as a complementary
    // half-warp-predicated LDG pair.
    float m = -3.402823466e+38f;
    #pragma unroll
    for (int s = 0; s < N_SPH; s++) {
        const float cx = lc[s * 3 + 0];
        const float cy = lc[s * 3 + 1];
        const float cz = lc[s * 3 + 2];
        const float x = fmaf(r00, cx, fmaf(r01, cy, fmaf(r02, cz, px)));
        const float y = fmaf(r10, cx, fmaf(r11, cy, fmaf(r12, cz, py)));
        const float z = fmaf(r20, cx, fmaf(r21, cy, fmaf(r22, cz, pz)));
        const float v = gather_split(sdf + ((vox(x) << 16) | (vox(y) << 8) | vox(z)), lane);
        m = fmaxf(m, lr[s] - v);
    }

    // clip(m - 0.01, 0, 0.5) / 0.25
    float res = fminf(fmaxf(m - 0.01f, 0.0f), 0.5f) * 4.0f;

    // sum over the 8 links (adjacent lanes within the warp)
    res += __shfl_xor_sync(0xffffffffu, res, 1);
    res += __shfl_xor_sync(0xffffffffu, res, 2);
    res += __shfl_xor_sync(0xffffffffu, res, 4);

    if (l == 0) out[g >> 3] = __ldg(wptr) * res;
}

extern "C" void kernel_launch(void* const* d_in, const int* in_sizes, int n_in,
                              void* d_out, int out_size) {
    const float* pos = (const float*)d_in[0];
    const float* rot = (const float*)d_in[1];
    const float* cen = (const float*)d_in[2];
    const float* rad = (const float*)d_in[3];
    const float* sdf = (const float*)d_in[4];
    const float* w   = (const float*)d_in[5];
    float* out = (float*)d_out;

    voxel_collision_kernel<<<1024, TB>>>(pos, rot, cen, rad, sdf, w, out);
}

// round 11
// speedup vs baseline: 1.0021x; 1.0021x over previous
#include <cuda_runtime.h>

// Inputs (metadata order):
//  0: link_pos_seq   [1024,32,8,3]    f32
//  1: link_rot_seq   [1024,32,8,3,3]  f32
//  2: sphere_centers [8,8,3]          f32
//  3: sphere_radii   [8,8]            f32
//  4: sdf_grid       [256,256,256]    f32
//  5: weight         scalar           f32
// Output: [1024,32] f32

#define GRID_N 256
#define N_LINKS 8
#define N_SPH 8

__global__ __launch_bounds__(256, 8)
void voxel_collision_kernel(const float* __restrict__ pos,
                            const float* __restrict__ rot,
                            const float* __restrict__ cen,
                            const float* __restrict__ rad,
                            const float* __restrict__ sdf,
                            const float* __restrict__ wptr,
                            float* __restrict__ out) {
    __shared__ float s_cen[N_LINKS * N_SPH * 3];   // 192 floats
    __shared__ float s_rad[N_LINKS * N_SPH];       // 64 floats

    const int tid = threadIdx.x;
    if (tid < N_LINKS * N_SPH * 3) s_cen[tid] = cen[tid];
    if (tid < N_LINKS * N_SPH)     s_rad[tid] = rad[tid];
    __syncthreads();

    const int g = blockIdx.x * 256 + tid;          // 0 .. 262143 = bh*8 + l
    const int l = g & 7;

    // Load rotation (9 consecutive floats) and position (3 consecutive floats).
    const float* R = rot + (size_t)g * 9;
    const float r00 = __ldg(R + 0), r01 = __ldg(R + 1), r02 = __ldg(R + 2);
    const float r10 = __ldg(R + 3), r11 = __ldg(R + 4), r12 = __ldg(R + 5);
    const float r20 = __ldg(R + 6), r21 = __ldg(R + 7), r22 = __ldg(R + 8);
    const float* P = pos + (size_t)g * 3;
    const float px = __ldg(P + 0), py = __ldg(P + 1), pz = __ldg(P + 2);

    const float* lc = s_cen + l * (N_SPH * 3);
    const float* lr = s_rad + l * N_SPH;

    float m = -3.402823466e+38f;
    #pragma unroll
    for (int s = 0; s < N_SPH; s++) {
        const float cx = lc[s * 3 + 0];
        const float cy = lc[s * 3 + 1];
        const float cz = lc[s * 3 + 2];
        // world point = R @ c + p
        const float x = fmaf(r00, cx, fmaf(r01, cy, fmaf(r02, cz, px)));
        const float y = fmaf(r10, cx, fmaf(r11, cy, fmaf(r12, cz, py)));
        const float z = fmaf(r20, cx, fmaf(r21, cy, fmaf(r22, cz, pz)));
        // voxel index: floor((p - (-1.28)) / 0.01), clipped to [0,255].
        // IEEE division to exactly match XLA (fast-math recip could flip floor).
        int i0 = (int)floorf(__fdiv_rn(x + 1.28f, 0.01f));
        int i1 = (int)floorf(__fdiv_rn(y + 1.28f, 0.01f));
        int i2 = (int)floorf(__fdiv_rn(z + 1.28f, 0.01f));
        i0 = min(max(i0, 0), GRID_N - 1);
        i1 = min(max(i1, 0), GRID_N - 1);
        i2 = min(max(i2, 0), GRID_N - 1);
        const float v = __ldg(sdf + (((size_t)i0 << 16) | (i1 << 8) | i2));
        m = fmaxf(m, lr[s] - v);
    }

    // threshold / clamp / normalize: clip(m - 0.01, 0, 0.5) / 0.25
    float res = fminf(fmaxf(m - 0.01f, 0.0f), 0.5f) * 4.0f;

    // sum over the 8 links (adjacent lanes within the warp)
    res += __shfl_xor_sync(0xffffffffu, res, 1);
    res += __shfl_xor_sync(0xffffffffu, res, 2);
    res += __shfl_xor_sync(0xffffffffu, res, 4);

    if (l == 0) out[g >> 3] = __ldg(wptr) * res;
}

extern "C" void kernel_launch(void* const* d_in, const int* in_sizes, int n_in,
                              void* d_out, int out_size) {
    const float* pos = (const float*)d_in[0];
    const float* rot = (const float*)d_in[1];
    const float* cen = (const float*)d_in[2];
    const float* rad = (const float*)d_in[3];
    const float* sdf = (const float*)d_in[4];
    const float* w   = (const float*)d_in[5];
    float* out = (float*)d_out;

    // 1024*32*8 = 262144 threads, 256 per block
    voxel_collision_kernel<<<1024, 256>>>(pos, rot, cen, rad, sdf, w, out);
}

// round 12
// speedup vs baseline: 1.0172x; 1.0151x over previous
#include <cuda_runtime.h>

// Inputs (metadata order):
//  0: link_pos_seq   [1024,32,8,3]    f32
//  1: link_rot_seq   [1024,32,8,3,3]  f32
//  2: sphere_centers [8,8,3]          f32
//  3: sphere_radii   [8,8]            f32
//  4: sdf_grid       [256,256,256]    f32
//  5: weight         scalar           f32
// Output: [1024,32] f32

#define GRID_N 256
#define N_LINKS 8
#define N_SPH 8

// L2-only gather (no L1 allocation): random 4B picks from a 64MB grid have
// zero L1 reuse, so skip the L1 fill/tag work on the bottleneck pipe.
__device__ __forceinline__ float ldcg(const float* p) {
    float v;
    asm volatile("ld.global.cg.f32 %0, [%1];" : "=f"(v) : "l"(p));
    return v;
}

__global__ __launch_bounds__(256, 8)
void voxel_collision_kernel(const float* __restrict__ pos,
                            const float* __restrict__ rot,
                            const float* __restrict__ cen,
                            const float* __restrict__ rad,
                            const float* __restrict__ sdf,
                            const float* __restrict__ wptr,
                            float* __restrict__ out) {
    __shared__ float s_cen[N_LINKS * N_SPH * 3];   // 192 floats
    __shared__ float s_rad[N_LINKS * N_SPH];       // 64 floats

    const int tid = threadIdx.x;
    if (tid < N_LINKS * N_SPH * 3) s_cen[tid] = cen[tid];
    if (tid < N_LINKS * N_SPH)     s_rad[tid] = rad[tid];
    __syncthreads();

    const int g = blockIdx.x * 256 + tid;          // 0 .. 262143 = bh*8 + l
    const int l = g & 7;

    // Load rotation (9 consecutive floats) and position (3 consecutive floats).
    const float* R = rot + (size_t)g * 9;
    const float r00 = __ldg(R + 0), r01 = __ldg(R + 1), r02 = __ldg(R + 2);
    const float r10 = __ldg(R + 3), r11 = __ldg(R + 4), r12 = __ldg(R + 5);
    const float r20 = __ldg(R + 6), r21 = __ldg(R + 7), r22 = __ldg(R + 8);
    const float* P = pos + (size_t)g * 3;
    const float px = __ldg(P + 0), py = __ldg(P + 1), pz = __ldg(P + 2);

    const float* lc = s_cen + l * (N_SPH * 3);
    const float* lr = s_rad + l * N_SPH;

    float m = -3.402823466e+38f;
    #pragma unroll
    for (int s = 0; s < N_SPH; s++) {
        const float cx = lc[s * 3 + 0];
        const float cy = lc[s * 3 + 1];
        const float cz = lc[s * 3 + 2];
        // world point = R @ c + p
        const float x = fmaf(r00, cx, fmaf(r01, cy, fmaf(r02, cz, px)));
        const float y = fmaf(r10, cx, fmaf(r11, cy, fmaf(r12, cz, py)));
        const float z = fmaf(r20, cx, fmaf(r21, cy, fmaf(r22, cz, pz)));
        // voxel index: floor((p - (-1.28)) / 0.01), clipped to [0,255].
        // IEEE division to exactly match XLA (fast-math recip could flip floor).
        int i0 = (int)floorf(__fdiv_rn(x + 1.28f, 0.01f));
        int i1 = (int)floorf(__fdiv_rn(y + 1.28f, 0.01f));
        int i2 = (int)floorf(__fdiv_rn(z + 1.28f, 0.01f));
        i0 = min(max(i0, 0), GRID_N - 1);
        i1 = min(max(i1, 0), GRID_N - 1);
        i2 = min(max(i2, 0), GRID_N - 1);
        const float v = ldcg(sdf + (((size_t)i0 << 16) | (i1 << 8) | i2));
        m = fmaxf(m, lr[s] - v);
    }

    // threshold / clamp / normalize: clip(m - 0.01, 0, 0.5) / 0.25
    float res = fminf(fmaxf(m - 0.01f, 0.0f), 0.5f) * 4.0f;

    // sum over the 8 links (adjacent lanes within the warp)
    res += __shfl_xor_sync(0xffffffffu, res, 1);
    res += __shfl_xor_sync(0xffffffffu, res, 2);
    res += __shfl_xor_sync(0xffffffffu, res, 4);

    if (l == 0) out[g >> 3] = __ldg(wptr) * res;
}

extern "C" void kernel_launch(void* const* d_in, const int* in_sizes, int n_in,
                              void* d_out, int out_size) {
    const float* pos = (const float*)d_in[0];
    const float* rot = (const float*)d_in[1];
    const float* cen = (const float*)d_in[2];
    const float* rad = (const float*)d_in[3];
    const float* sdf = (const float*)d_in[4];
    const float* w   = (const float*)d_in[5];
    float* out = (float*)d_out;

    // 1024*32*8 = 262144 threads, 256 per block
    voxel_collision_kernel<<<1024, 256>>>(pos, rot, cen, rad, sdf, w, out);
}

// round 13
// speedup vs baseline: 1.0489x; 1.0311x over previous
#include <cuda_runtime.h>

// Inputs (metadata order):
//  0: link_pos_seq   [1024,32,8,3]    f32
//  1: link_rot_seq   [1024,32,8,3,3]  f32
//  2: sphere_centers [8,8,3]          f32
//  3: sphere_radii   [8,8]            f32
//  4: sdf_grid       [256,256,256]    f32
//  5: weight         scalar           f32
// Output: [1024,32] f32

#define GRID_N 256
#define N_LINKS 8
#define N_SPH 8

// L2-only gather (no L1 allocation): random 4B picks from a 64MB grid have
// zero L1 reuse, so skip the L1 fill/tag work on the bottleneck pipe.
__device__ __forceinline__ float ldcg(const float* p) {
    float v;
    asm volatile("ld.global.cg.f32 %0, [%1];" : "=f"(v) : "l"(p));
    return v;
}

// Faithfully-rounded t/0.01 in 3 instructions (mul + 2 fma Newton residual
// correction). <=1ulp from IEEE division; floor flips only at already-rare
// boundary cases (rel_err measured bit-identical to IEEE path: 1.95e-4).
__device__ __forceinline__ float div001(float t) {
    const float q0 = t * 100.0f;
    return fmaf(fmaf(-0.01f, q0, t), 100.0f, q0);
}

__device__ __forceinline__ int vox(float t) {
    int i = (int)floorf(div001(t + 1.28f));
    return min(max(i, 0), GRID_N - 1);
}

__global__ __launch_bounds__(256, 8)
void voxel_collision_kernel(const float* __restrict__ pos,
                            const float* __restrict__ rot,
                            const float* __restrict__ cen,
                            const float* __restrict__ rad,
                            const float* __restrict__ sdf,
                            const float* __restrict__ wptr,
                            float* __restrict__ out) {
    __shared__ float s_cen[N_LINKS * N_SPH * 3];   // 192 floats
    __shared__ float s_rad[N_LINKS * N_SPH];       // 64 floats

    const int tid = threadIdx.x;
    if (tid < N_LINKS * N_SPH * 3) s_cen[tid] = cen[tid];
    if (tid < N_LINKS * N_SPH)     s_rad[tid] = rad[tid];
    __syncthreads();

    const int g = blockIdx.x * 256 + tid;          // 0 .. 262143 = bh*8 + l
    const int l = g & 7;

    // Load rotation (9 consecutive floats) and position (3 consecutive floats).
    const float* R = rot + (size_t)g * 9;
    const float r00 = __ldg(R + 0), r01 = __ldg(R + 1), r02 = __ldg(R + 2);
    const float r10 = __ldg(R + 3), r11 = __ldg(R + 4), r12 = __ldg(R + 5);
    const float r20 = __ldg(R + 6), r21 = __ldg(R + 7), r22 = __ldg(R + 8);
    const float* P = pos + (size_t)g * 3;
    const float px = __ldg(P + 0), py = __ldg(P + 1), pz = __ldg(P + 2);

    const float* lc = s_cen + l * (N_SPH * 3);
    const float* lr = s_rad + l * N_SPH;

    float m = -3.402823466e+38f;
    #pragma unroll
    for (int s = 0; s < N_SPH; s++) {
        const float cx = lc[s * 3 + 0];
        const float cy = lc[s * 3 + 1];
        const float cz = lc[s * 3 + 2];
        // world point = R @ c + p
        const float x = fmaf(r00, cx, fmaf(r01, cy, fmaf(r02, cz, px)));
        const float y = fmaf(r10, cx, fmaf(r11, cy, fmaf(r12, cz, py)));
        const float z = fmaf(r20, cx, fmaf(r21, cy, fmaf(r22, cz, pz)));
        const float v = ldcg(sdf + ((vox(x) << 16) | (vox(y) << 8) | vox(z)));
        m = fmaxf(m, lr[s] - v);
    }

    // threshold / clamp / normalize: clip(m - 0.01, 0, 0.5) / 0.25
    float res = fminf(fmaxf(m - 0.01f, 0.0f), 0.5f) * 4.0f;

    // sum over the 8 links (adjacent lanes within the warp)
    res += __shfl_xor_sync(0xffffffffu, res, 1);
    res += __shfl_xor_sync(0xffffffffu, res, 2);
    res += __shfl_xor_sync(0xffffffffu, res, 4);

    if (l == 0) out[g >> 3] = __ldg(wptr) * res;
}

extern "C" void kernel_launch(void* const* d_in, const int* in_sizes, int n_in,
                              void* d_out, int out_size) {
    const float* pos = (const float*)d_in[0];
    const float* rot = (const float*)d_in[1];
    const float* cen = (const float*)d_in[2];
    const float* rad = (const float*)d_in[3];
    const float* sdf = (const float*)d_in[4];
    const float* w   = (const float*)d_in[5];
    float* out = (float*)d_out;

    // 1024*32*8 = 262144 threads, 256 per block
    voxel_collision_kernel<<<1024, 256>>>(pos, rot, cen, rad, sdf, w, out);
}